// round 8
// baseline (speedup 1.0000x reference)
#include <cuda_runtime.h>

#define N_NODES 50000
#define E_MAX   1600000
#define GEMM1_BLOCKS ((N_NODES + 63) / 64)          // 782

// ---------------- scratch (static device globals; no allocation) -------------
__device__ int    g_deg[N_NODES];        // REAL in-degree count; reset to 0 by k_scan each run
__device__ float  g_dis[N_NODES];
__device__ int    g_src[E_MAX];
__device__ int    g_dst[E_MAX];
__device__ int    g_offs[N_NODES + 1];   // CSR offsets by dst (real edges only)
__device__ int    g_cur[N_NODES];        // bucket cursors
__device__ int    g_csr_src[E_MAX];      // src ids grouped by dst
__device__ float2 g_hs [N_NODES * 32];   // dis[src]-scaled x@W1, 64 f32/node
__device__ float  g_hs2[N_NODES * 32];   // dis-scaled h@W2, 32 f32/node

// ---------------- prep: dtype detect + edge parse + degree count -------------
// int64 layout: odd int32 words are high words == 0. int32: random ids.
__global__ void k_prep_edges(const int* __restrict__ p, int E) {
    __shared__ int s_nonzero;
    if (threadIdx.x == 0) s_nonzero = 0;
    __syncthreads();
    if (threadIdx.x < 256) {
        if (p[2 * threadIdx.x + 1] != 0) atomicOr(&s_nonzero, 1);
    }
    __syncthreads();
    int i64 = (s_nonzero == 0);

    int e = blockIdx.x * blockDim.x + threadIdx.x;
    if (e >= E) return;
    int s, d;
    if (i64) { s = p[2 * e]; d = p[2 * (E + e)]; }
    else     { s = p[e];     d = p[E + e]; }
    if ((unsigned)s >= N_NODES) s = 0;
    if ((unsigned)d >= N_NODES) d = 0;
    g_src[e] = s;
    g_dst[e] = d;
    atomicAdd(&g_deg[d], 1);
}

// ---------------- scan: offs/cur prefix, dis=rsqrt(cnt+1), deg reset ---------
#define SCAN_T 1024
#define SCAN_CH ((N_NODES + SCAN_T - 1) / SCAN_T)   // 49
__global__ void k_scan() {
    __shared__ int partial[SCAN_T];
    int t = threadIdx.x;
    int base = t * SCAN_CH;
    int sum = 0;
#pragma unroll 4
    for (int i = 0; i < SCAN_CH; i++) {
        int idx = base + i;
        if (idx < N_NODES) sum += g_deg[idx];
    }
    partial[t] = sum;
    __syncthreads();
    for (int off = 1; off < SCAN_T; off <<= 1) {
        int v = (t >= off) ? partial[t - off] : 0;
        __syncthreads();
        partial[t] += v;
        __syncthreads();
    }
    int run = (t == 0) ? 0 : partial[t - 1];
    for (int i = 0; i < SCAN_CH; i++) {
        int idx = base + i;
        if (idx < N_NODES) {
            int cnt = g_deg[idx];
            g_deg[idx] = 0;                       // restore zero-state invariant
            g_offs[idx] = run;
            g_cur[idx]  = run;
            g_dis[idx]  = rsqrtf((float)(cnt + 1));  // +1 = self loop
            run += cnt;
        }
    }
    if (t == SCAN_T - 1) g_offs[N_NODES] = partial[SCAN_T - 1];
}

// ---------------- fused: GEMM1 (blocks < GEMM1_BLOCKS) + bucket (rest) -------
// GEMM1: hs = dis * (x @ W1). 256 threads, 64x64 tile, thread = 2 rows x 8 cols.
__global__ void k_gemm1_bucket(const float* __restrict__ x,
                               const float* __restrict__ W, int E) {
    if (blockIdx.x < GEMM1_BLOCKS) {
        __shared__ float sWT[64 * 132];
        int t = threadIdx.x;                     // 0..255
        for (int idx = t; idx < 128 * 64; idx += 256) {
            int k = idx >> 6, c = idx & 63;
            sWT[c * 132 + k] = W[idx];
        }
        __syncthreads();

        int rbase = blockIdx.x * 64 + (t >> 3);  // + 32*i, i<2
        int cbase = t & 7;                       // + 8*j, j<8
        float acc[2][8];
#pragma unroll
        for (int i = 0; i < 2; i++)
#pragma unroll
            for (int j = 0; j < 8; j++) acc[i][j] = 0.f;

        for (int k = 0; k < 128; k += 4) {
            float4 b[8];
#pragma unroll
            for (int j = 0; j < 8; j++)
                b[j] = *(const float4*)&sWT[(cbase + 8 * j) * 132 + k];
#pragma unroll
            for (int i = 0; i < 2; i++) {
                int r = rbase + 32 * i;
                float4 a = (r < N_NODES) ? *(const float4*)&x[r * 128 + k]
                                         : make_float4(0.f, 0.f, 0.f, 0.f);
#pragma unroll
                for (int j = 0; j < 8; j++) {
                    acc[i][j] += a.x * b[j].x;
                    acc[i][j] += a.y * b[j].y;
                    acc[i][j] += a.z * b[j].z;
                    acc[i][j] += a.w * b[j].w;
                }
            }
        }

        float* hs = (float*)g_hs;
#pragma unroll
        for (int i = 0; i < 2; i++) {
            int r = rbase + 32 * i;
            if (r < N_NODES) {
                float dv = g_dis[r];
#pragma unroll
                for (int j = 0; j < 8; j++)
                    hs[r * 64 + cbase + 8 * j] = dv * acc[i][j];
            }
        }
    } else {
        int e = (blockIdx.x - GEMM1_BLOCKS) * 256 + threadIdx.x;
        if (e >= E) return;
        int d = g_dst[e];
        int pos = atomicAdd(&g_cur[d], 1);
        g_csr_src[pos] = g_src[e];
    }
}

// ---------------- gather layer 1 (+tanh fused): one warp per node ------------
// 32 lanes x float2 = full 64-float row. Indices: one coalesced 32-wide load,
// broadcast by shfl. Fast path: fully unrolled 32-edge batch (32 LDGs in flight).
__global__ void k_gather1(float* __restrict__ hout) {
    int w = (blockIdx.x * blockDim.x + threadIdx.x) >> 5;   // node
    if (w >= N_NODES) return;
    int lane = threadIdx.x & 31;
    const float2* __restrict__ hs = g_hs;
    const int* __restrict__ cs = g_csr_src;

    float2 acc = hs[w * 32 + lane];              // self-loop message
    int beg = g_offs[w], end = g_offs[w + 1];

    for (int base = beg; base < end; base += 32) {
        int n = end - base;
        int idx = (base + lane < end) ? cs[base + lane] : 0;
        if (n >= 32) {
#pragma unroll
            for (int i = 0; i < 32; i++) {
                int s = __shfl_sync(0xffffffffu, idx, i);
                float2 a = hs[s * 32 + lane];
                acc.x += a.x; acc.y += a.y;
            }
        } else {
            for (int i = 0; i < n; i++) {
                int s = __shfl_sync(0xffffffffu, idx, i);
                float2 a = hs[s * 32 + lane];
                acc.x += a.x; acc.y += a.y;
            }
        }
    }

    float dv = g_dis[w];
    float2 o;
    o.x = tanhf(dv * acc.x);
    o.y = tanhf(dv * acc.y);
    ((float2*)hout)[w * 32 + lane] = o;
}

// ---------------- GEMM2: hs2 = dis * (h @ W2) --------------------------------
__global__ void k_gemm2(const float* __restrict__ h, const float* __restrict__ W) {
    __shared__ float sWT[32 * 68];
    int t = threadIdx.x;                         // 0..127
    for (int idx = t; idx < 64 * 32; idx += 128) {
        int k = idx >> 5, c = idx & 31;
        sWT[c * 68 + k] = W[idx];
    }
    __syncthreads();

    int rbase = blockIdx.x * 64 + (t >> 3);
    int cbase = t & 7;
    float acc[4][4];
#pragma unroll
    for (int i = 0; i < 4; i++)
#pragma unroll
        for (int j = 0; j < 4; j++) acc[i][j] = 0.f;

    for (int k = 0; k < 64; k += 4) {
        float4 b[4];
#pragma unroll
        for (int j = 0; j < 4; j++)
            b[j] = *(const float4*)&sWT[(cbase + 8 * j) * 68 + k];
#pragma unroll
        for (int i = 0; i < 4; i++) {
            int r = rbase + 16 * i;
            float4 a = (r < N_NODES) ? *(const float4*)&h[r * 64 + k]
                                     : make_float4(0.f, 0.f, 0.f, 0.f);
#pragma unroll
            for (int j = 0; j < 4; j++) {
                acc[i][j] += a.x * b[j].x;
                acc[i][j] += a.y * b[j].y;
                acc[i][j] += a.z * b[j].z;
                acc[i][j] += a.w * b[j].w;
            }
        }
    }

#pragma unroll
    for (int i = 0; i < 4; i++) {
        int r = rbase + 16 * i;
        if (r < N_NODES) {
            float dv = g_dis[r];
#pragma unroll
            for (int j = 0; j < 4; j++)
                g_hs2[r * 32 + cbase + 8 * j] = dv * acc[i][j];
        }
    }
}

// ---------------- gather layer 2 (+final scale): one warp per node -----------
__global__ void k_gather2(float* __restrict__ out) {
    int w = (blockIdx.x * blockDim.x + threadIdx.x) >> 5;
    if (w >= N_NODES) return;
    int lane = threadIdx.x & 31;
    const float* __restrict__ hs2 = g_hs2;
    const int* __restrict__ cs = g_csr_src;

    float acc = hs2[w * 32 + lane];
    int beg = g_offs[w], end = g_offs[w + 1];

    for (int base = beg; base < end; base += 32) {
        int n = end - base;
        int idx = (base + lane < end) ? cs[base + lane] : 0;
        if (n >= 32) {
#pragma unroll
            for (int i = 0; i < 32; i++) {
                int s = __shfl_sync(0xffffffffu, idx, i);
                acc += hs2[s * 32 + lane];
            }
        } else {
            for (int i = 0; i < n; i++) {
                int s = __shfl_sync(0xffffffffu, idx, i);
                acc += hs2[s * 32 + lane];
            }
        }
    }

    out[w * 32 + lane] = g_dis[w] * acc;
}

// ---------------- launch ------------------------------------------------------
extern "C" void kernel_launch(void* const* d_in, const int* in_sizes, int n_in,
                              void* d_out, int out_size) {
    const float* x  = (const float*)d_in[0];
    const int*   ei = (const int*)d_in[1];
    const float* W1 = (const float*)d_in[2];
    const float* W2 = (const float*)d_in[3];

    float* out  = (float*)d_out;          // [N,32]
    float* hout = out + N_NODES * 32;     // [N,64]

    int E = in_sizes[1] / 2;
    if (E > E_MAX) E = E_MAX;

    int bucket_blocks = (E + 255) / 256;

    k_prep_edges<<<(E + 255) / 256, 256>>>(ei, E);                 // 1
    k_scan<<<1, SCAN_T>>>();                                       // 2
    k_gemm1_bucket<<<GEMM1_BLOCKS + bucket_blocks, 256>>>(x, W1, E); // 3
    k_gather1<<<(N_NODES * 32 + 255) / 256, 256>>>(hout);          // 4  <- ncu capture
    k_gemm2<<<(N_NODES + 63) / 64, 128>>>(hout, W2);               // 5
    k_gather2<<<(N_NODES * 32 + 255) / 256, 256>>>(out);           // 6
}

// round 9
// speedup vs baseline: 1.6507x; 1.6507x over previous
#include <cuda_runtime.h>

#define N_NODES 50000
#define E_MAX   1600000
#define NBLK    ((N_NODES + 255) / 256)   // 196

// ---------------- scratch (static device globals; no allocation) -------------
__device__ int    g_deg[N_NODES];        // in-degree count; reset to 0 by k_scanB
__device__ int    g_bsum[NBLK];          // per-block degree sums
__device__ float  g_dis[N_NODES];
__device__ int    g_src[E_MAX];
__device__ int    g_dst[E_MAX];
__device__ int    g_offs[N_NODES + 1];   // CSR offsets by dst (real edges only)
__device__ int    g_cur[N_NODES];        // bucket cursors
__device__ int    g_csr_src[E_MAX];      // src ids grouped by dst
__device__ float2 g_hs [N_NODES * 32];   // dis[src]-scaled x@W1, 64 f32/node
__device__ float  g_hs2[N_NODES * 32];   // dis-scaled h@W2, 32 f32/node

// ---------------- prep: dtype detect + edge parse + degree count -------------
__global__ void k_prep_edges(const int* __restrict__ p, int E) {
    __shared__ int s_nonzero;
    if (threadIdx.x == 0) s_nonzero = 0;
    __syncthreads();
    if (threadIdx.x < 256) {
        if (p[2 * threadIdx.x + 1] != 0) atomicOr(&s_nonzero, 1);
    }
    __syncthreads();
    int i64 = (s_nonzero == 0);

    int e = blockIdx.x * blockDim.x + threadIdx.x;
    if (e >= E) return;
    int s, d;
    if (i64) { s = p[2 * e]; d = p[2 * (E + e)]; }
    else     { s = p[e];     d = p[E + e]; }
    if ((unsigned)s >= N_NODES) s = 0;
    if ((unsigned)d >= N_NODES) d = 0;
    g_src[e] = s;
    g_dst[e] = d;
    atomicAdd(&g_deg[d], 1);
}

// ---------------- scan phase A: per-block degree sums ------------------------
__global__ void k_scanA() {
    __shared__ int red[256];
    int t = threadIdx.x;
    int i = blockIdx.x * 256 + t;
    red[t] = (i < N_NODES) ? g_deg[i] : 0;
    __syncthreads();
#pragma unroll
    for (int off = 128; off > 0; off >>= 1) {
        if (t < off) red[t] += red[t + off];
        __syncthreads();
    }
    if (t == 0) g_bsum[blockIdx.x] = red[0];
}

// ---------------- scan phase B: block prefix + local scan + writes -----------
__global__ void k_scanB() {
    __shared__ int red[256];
    __shared__ int sc[256];
    int t = threadIdx.x;
    int b = blockIdx.x;

    // exclusive prefix of block sums: sum of g_bsum[0..b)
    red[t] = (t < b) ? g_bsum[t] : 0;     // NBLK=196 < 256
    __syncthreads();
#pragma unroll
    for (int off = 128; off > 0; off >>= 1) {
        if (t < off) red[t] += red[t + off];
        __syncthreads();
    }
    int block_off = red[0];

    // local exclusive scan of this block's 256 degrees (Hillis-Steele)
    int i = b * 256 + t;
    int d = (i < N_NODES) ? g_deg[i] : 0;
    sc[t] = d;
    __syncthreads();
#pragma unroll
    for (int off = 1; off < 256; off <<= 1) {
        int v = (t >= off) ? sc[t - off] : 0;
        __syncthreads();
        sc[t] += v;
        __syncthreads();
    }
    int off = block_off + sc[t] - d;      // exclusive

    if (i < N_NODES) {
        g_offs[i] = off;
        g_cur[i]  = off;
        g_dis[i]  = rsqrtf((float)(d + 1));   // +1 = self loop
        g_deg[i]  = 0;                        // restore zero-state invariant
        if (i == N_NODES - 1) g_offs[N_NODES] = off + d;
    }
}

// ---------------- bucket edges by dst ----------------------------------------
__global__ void k_bucket(int E) {
    int e = blockIdx.x * blockDim.x + threadIdx.x;
    if (e >= E) return;
    int d = g_dst[e];
    int pos = atomicAdd(&g_cur[d], 1);
    g_csr_src[pos] = g_src[e];
}

// ---------------- GEMM1: hs = dis * (x @ W1) ---------------------------------
// 256 threads, 64x64 tile, thread = 2 rows x 8 cols.
__global__ void k_gemm1(const float* __restrict__ x, const float* __restrict__ W) {
    __shared__ float sWT[64 * 132];
    int t = threadIdx.x;                     // 0..255
    for (int idx = t; idx < 128 * 64; idx += 256) {
        int k = idx >> 6, c = idx & 63;
        sWT[c * 132 + k] = W[idx];
    }
    __syncthreads();

    int rbase = blockIdx.x * 64 + (t >> 3);  // + 32*i, i<2
    int cbase = t & 7;                       // + 8*j, j<8
    float acc[2][8];
#pragma unroll
    for (int i = 0; i < 2; i++)
#pragma unroll
        for (int j = 0; j < 8; j++) acc[i][j] = 0.f;

    for (int k = 0; k < 128; k += 4) {
        float4 b[8];
#pragma unroll
        for (int j = 0; j < 8; j++)
            b[j] = *(const float4*)&sWT[(cbase + 8 * j) * 132 + k];
#pragma unroll
        for (int i = 0; i < 2; i++) {
            int r = rbase + 32 * i;
            float4 a = (r < N_NODES) ? *(const float4*)&x[r * 128 + k]
                                     : make_float4(0.f, 0.f, 0.f, 0.f);
#pragma unroll
            for (int j = 0; j < 8; j++) {
                acc[i][j] += a.x * b[j].x;
                acc[i][j] += a.y * b[j].y;
                acc[i][j] += a.z * b[j].z;
                acc[i][j] += a.w * b[j].w;
            }
        }
    }

    float* hs = (float*)g_hs;
#pragma unroll
    for (int i = 0; i < 2; i++) {
        int r = rbase + 32 * i;
        if (r < N_NODES) {
            float dv = g_dis[r];
#pragma unroll
            for (int j = 0; j < 8; j++)
                hs[r * 64 + cbase + 8 * j] = dv * acc[i][j];
        }
    }
}

// ---------------- gather layer 1 (+tanh fused): one warp per node ------------
__global__ void k_gather1(float* __restrict__ hout) {
    int w = (blockIdx.x * blockDim.x + threadIdx.x) >> 5;   // node
    if (w >= N_NODES) return;
    int lane = threadIdx.x & 31;
    const float2* __restrict__ hs = g_hs;
    const int* __restrict__ cs = g_csr_src;

    float2 acc = hs[w * 32 + lane];              // self-loop message
    int beg = g_offs[w], end = g_offs[w + 1];

    for (int base = beg; base < end; base += 32) {
        int n = end - base;
        int idx = (base + lane < end) ? cs[base + lane] : 0;
        if (n >= 32) {
#pragma unroll
            for (int i = 0; i < 32; i++) {
                int s = __shfl_sync(0xffffffffu, idx, i);
                float2 a = hs[s * 32 + lane];
                acc.x += a.x; acc.y += a.y;
            }
        } else {
            for (int i = 0; i < n; i++) {
                int s = __shfl_sync(0xffffffffu, idx, i);
                float2 a = hs[s * 32 + lane];
                acc.x += a.x; acc.y += a.y;
            }
        }
    }

    float dv = g_dis[w];
    float2 o;
    o.x = tanhf(dv * acc.x);
    o.y = tanhf(dv * acc.y);
    ((float2*)hout)[w * 32 + lane] = o;
}

// ---------------- GEMM2: hs2 = dis * (h @ W2) --------------------------------
__global__ void k_gemm2(const float* __restrict__ h, const float* __restrict__ W) {
    __shared__ float sWT[32 * 68];
    int t = threadIdx.x;                         // 0..127
    for (int idx = t; idx < 64 * 32; idx += 128) {
        int k = idx >> 5, c = idx & 31;
        sWT[c * 68 + k] = W[idx];
    }
    __syncthreads();

    int rbase = blockIdx.x * 64 + (t >> 3);
    int cbase = t & 7;
    float acc[4][4];
#pragma unroll
    for (int i = 0; i < 4; i++)
#pragma unroll
        for (int j = 0; j < 4; j++) acc[i][j] = 0.f;

    for (int k = 0; k < 64; k += 4) {
        float4 b[4];
#pragma unroll
        for (int j = 0; j < 4; j++)
            b[j] = *(const float4*)&sWT[(cbase + 8 * j) * 68 + k];
#pragma unroll
        for (int i = 0; i < 4; i++) {
            int r = rbase + 16 * i;
            float4 a = (r < N_NODES) ? *(const float4*)&h[r * 64 + k]
                                     : make_float4(0.f, 0.f, 0.f, 0.f);
#pragma unroll
            for (int j = 0; j < 4; j++) {
                acc[i][j] += a.x * b[j].x;
                acc[i][j] += a.y * b[j].y;
                acc[i][j] += a.z * b[j].z;
                acc[i][j] += a.w * b[j].w;
            }
        }
    }

#pragma unroll
    for (int i = 0; i < 4; i++) {
        int r = rbase + 16 * i;
        if (r < N_NODES) {
            float dv = g_dis[r];
#pragma unroll
            for (int j = 0; j < 4; j++)
                g_hs2[r * 32 + cbase + 8 * j] = dv * acc[i][j];
        }
    }
}

// ---------------- gather layer 2 (+final scale): one warp per node -----------
__global__ void k_gather2(float* __restrict__ out) {
    int w = (blockIdx.x * blockDim.x + threadIdx.x) >> 5;
    if (w >= N_NODES) return;
    int lane = threadIdx.x & 31;
    const float* __restrict__ hs2 = g_hs2;
    const int* __restrict__ cs = g_csr_src;

    float acc = hs2[w * 32 + lane];
    int beg = g_offs[w], end = g_offs[w + 1];

    for (int base = beg; base < end; base += 32) {
        int n = end - base;
        int idx = (base + lane < end) ? cs[base + lane] : 0;
        if (n >= 32) {
#pragma unroll
            for (int i = 0; i < 32; i++) {
                int s = __shfl_sync(0xffffffffu, idx, i);
                acc += hs2[s * 32 + lane];
            }
        } else {
            for (int i = 0; i < n; i++) {
                int s = __shfl_sync(0xffffffffu, idx, i);
                acc += hs2[s * 32 + lane];
            }
        }
    }

    out[w * 32 + lane] = g_dis[w] * acc;
}

// ---------------- launch ------------------------------------------------------
extern "C" void kernel_launch(void* const* d_in, const int* in_sizes, int n_in,
                              void* d_out, int out_size) {
    const float* x  = (const float*)d_in[0];
    const int*   ei = (const int*)d_in[1];
    const float* W1 = (const float*)d_in[2];
    const float* W2 = (const float*)d_in[3];

    float* out  = (float*)d_out;          // [N,32]
    float* hout = out + N_NODES * 32;     // [N,64]

    int E = in_sizes[1] / 2;
    if (E > E_MAX) E = E_MAX;

    k_prep_edges<<<(E + 255) / 256, 256>>>(ei, E);          // 1
    k_scanA<<<NBLK, 256>>>();                               // 2
    k_scanB<<<NBLK, 256>>>();                               // 3
    k_gemm1<<<(N_NODES + 63) / 64, 256>>>(x, W1);           // 4  <- ncu capture
    k_bucket<<<(E + 255) / 256, 256>>>(E);                  // 5
    k_gather1<<<(N_NODES * 32 + 255) / 256, 256>>>(hout);   // 6
    k_gemm2<<<(N_NODES + 63) / 64, 128>>>(hout, W2);        // 7
    k_gather2<<<(N_NODES * 32 + 255) / 256, 256>>>(out);    // 8
}

// round 10
// speedup vs baseline: 1.7763x; 1.0761x over previous
#include <cuda_runtime.h>

#define N_NODES 50000
#define E_MAX   1600000
#define NBLK    ((N_NODES + 255) / 256)   // 196

// ---------------- scratch (static device globals; no allocation) -------------
__device__ int    g_deg[N_NODES];        // in-degree count; reset to 0 by k_scanB
__device__ int    g_bsum[NBLK];          // per-block degree sums
__device__ float  g_dis[N_NODES];
__device__ int    g_src[E_MAX];
__device__ int    g_dst[E_MAX];
__device__ int    g_offs[N_NODES + 1];   // CSR offsets by dst (real edges only)
__device__ int    g_cur[N_NODES];        // bucket cursors
__device__ int    g_csr_src[E_MAX];      // src ids grouped by dst
__device__ float2 g_hs [N_NODES * 32];   // dis[src]-scaled x@W1, 64 f32/node
__device__ float  g_hs2[N_NODES * 32];   // dis-scaled h@W2, 32 f32/node

// ---------------- prep: dtype detect + edge parse + degree count -------------
__global__ void k_prep_edges(const int* __restrict__ p, int E) {
    __shared__ int s_nonzero;
    if (threadIdx.x == 0) s_nonzero = 0;
    __syncthreads();
    if (threadIdx.x < 256) {
        if (p[2 * threadIdx.x + 1] != 0) atomicOr(&s_nonzero, 1);
    }
    __syncthreads();
    int i64 = (s_nonzero == 0);

    int e = blockIdx.x * blockDim.x + threadIdx.x;
    if (e >= E) return;
    int s, d;
    if (i64) { s = p[2 * e]; d = p[2 * (E + e)]; }
    else     { s = p[e];     d = p[E + e]; }
    if ((unsigned)s >= N_NODES) s = 0;
    if ((unsigned)d >= N_NODES) d = 0;
    g_src[e] = s;
    g_dst[e] = d;
    atomicAdd(&g_deg[d], 1);
}

// ---------------- scan phase A: per-block degree sums ------------------------
__global__ void k_scanA() {
    __shared__ int red[256];
    int t = threadIdx.x;
    int i = blockIdx.x * 256 + t;
    red[t] = (i < N_NODES) ? g_deg[i] : 0;
    __syncthreads();
#pragma unroll
    for (int off = 128; off > 0; off >>= 1) {
        if (t < off) red[t] += red[t + off];
        __syncthreads();
    }
    if (t == 0) g_bsum[blockIdx.x] = red[0];
}

// ---------------- scan phase B: block prefix + local scan + writes -----------
__global__ void k_scanB() {
    __shared__ int red[256];
    __shared__ int sc[256];
    int t = threadIdx.x;
    int b = blockIdx.x;

    red[t] = (t < b) ? g_bsum[t] : 0;     // NBLK=196 < 256
    __syncthreads();
#pragma unroll
    for (int off = 128; off > 0; off >>= 1) {
        if (t < off) red[t] += red[t + off];
        __syncthreads();
    }
    int block_off = red[0];

    int i = b * 256 + t;
    int d = (i < N_NODES) ? g_deg[i] : 0;
    sc[t] = d;
    __syncthreads();
#pragma unroll
    for (int off = 1; off < 256; off <<= 1) {
        int v = (t >= off) ? sc[t - off] : 0;
        __syncthreads();
        sc[t] += v;
        __syncthreads();
    }
    int off = block_off + sc[t] - d;      // exclusive

    if (i < N_NODES) {
        g_offs[i] = off;
        g_cur[i]  = off;
        g_dis[i]  = rsqrtf((float)(d + 1));   // +1 = self loop
        g_deg[i]  = 0;                        // restore zero-state invariant
        if (i == N_NODES - 1) g_offs[N_NODES] = off + d;
    }
}

// ---------------- bucket edges by dst ----------------------------------------
__global__ void k_bucket(int E) {
    int e = blockIdx.x * blockDim.x + threadIdx.x;
    if (e >= E) return;
    int d = g_dst[e];
    int pos = atomicAdd(&g_cur[d], 1);
    g_csr_src[pos] = g_src[e];
}

// ---------------- GEMM1: hs = dis * (x @ W1) ---------------------------------
// 256 threads, 128x64 tile, thread = 4 rows x 8 cols (amortizes LDS over 2x rows).
__global__ void k_gemm1(const float* __restrict__ x, const float* __restrict__ W) {
    __shared__ float sWT[64 * 132];
    int t = threadIdx.x;                     // 0..255
    for (int idx = t; idx < 128 * 64; idx += 256) {
        int k = idx >> 6, c = idx & 63;
        sWT[c * 132 + k] = W[idx];
    }
    __syncthreads();

    int rbase = blockIdx.x * 128 + (t >> 3); // + 32*i, i<4
    int cbase = t & 7;                       // + 8*j, j<8
    float acc[4][8];
#pragma unroll
    for (int i = 0; i < 4; i++)
#pragma unroll
        for (int j = 0; j < 8; j++) acc[i][j] = 0.f;

    for (int k = 0; k < 128; k += 4) {
        float4 b[8];
#pragma unroll
        for (int j = 0; j < 8; j++)
            b[j] = *(const float4*)&sWT[(cbase + 8 * j) * 132 + k];
#pragma unroll
        for (int i = 0; i < 4; i++) {
            int r = rbase + 32 * i;
            float4 a = (r < N_NODES) ? *(const float4*)&x[r * 128 + k]
                                     : make_float4(0.f, 0.f, 0.f, 0.f);
#pragma unroll
            for (int j = 0; j < 8; j++) {
                acc[i][j] += a.x * b[j].x;
                acc[i][j] += a.y * b[j].y;
                acc[i][j] += a.z * b[j].z;
                acc[i][j] += a.w * b[j].w;
            }
        }
    }

    float* hs = (float*)g_hs;
#pragma unroll
    for (int i = 0; i < 4; i++) {
        int r = rbase + 32 * i;
        if (r < N_NODES) {
            float dv = g_dis[r];
#pragma unroll
            for (int j = 0; j < 8; j++)
                hs[r * 64 + cbase + 8 * j] = dv * acc[i][j];
        }
    }
}

// ---------------- gather layer 1 (+tanh fused): one warp per node ------------
__global__ void k_gather1(float* __restrict__ hout) {
    int w = (blockIdx.x * blockDim.x + threadIdx.x) >> 5;   // node
    if (w >= N_NODES) return;
    int lane = threadIdx.x & 31;
    const float2* __restrict__ hs = g_hs;
    const int* __restrict__ cs = g_csr_src;

    float2 acc = hs[w * 32 + lane];              // self-loop message
    int beg = g_offs[w], end = g_offs[w + 1];

    for (int base = beg; base < end; base += 32) {
        int n = end - base;
        int idx = (base + lane < end) ? cs[base + lane] : 0;
        if (n >= 32) {
#pragma unroll
            for (int i = 0; i < 32; i++) {
                int s = __shfl_sync(0xffffffffu, idx, i);
                float2 a = hs[s * 32 + lane];
                acc.x += a.x; acc.y += a.y;
            }
        } else {
            for (int i = 0; i < n; i++) {
                int s = __shfl_sync(0xffffffffu, idx, i);
                float2 a = hs[s * 32 + lane];
                acc.x += a.x; acc.y += a.y;
            }
        }
    }

    float dv = g_dis[w];
    float2 o;
    o.x = tanhf(dv * acc.x);
    o.y = tanhf(dv * acc.y);
    ((float2*)hout)[w * 32 + lane] = o;
}

// ---------------- GEMM2: hs2 = dis * (h @ W2) --------------------------------
__global__ void k_gemm2(const float* __restrict__ h, const float* __restrict__ W) {
    __shared__ float sWT[32 * 68];
    int t = threadIdx.x;                         // 0..127
    for (int idx = t; idx < 64 * 32; idx += 128) {
        int k = idx >> 5, c = idx & 31;
        sWT[c * 68 + k] = W[idx];
    }
    __syncthreads();

    int rbase = blockIdx.x * 64 + (t >> 3);
    int cbase = t & 7;
    float acc[4][4];
#pragma unroll
    for (int i = 0; i < 4; i++)
#pragma unroll
        for (int j = 0; j < 4; j++) acc[i][j] = 0.f;

    for (int k = 0; k < 64; k += 4) {
        float4 b[4];
#pragma unroll
        for (int j = 0; j < 4; j++)
            b[j] = *(const float4*)&sWT[(cbase + 8 * j) * 68 + k];
#pragma unroll
        for (int i = 0; i < 4; i++) {
            int r = rbase + 16 * i;
            float4 a = (r < N_NODES) ? *(const float4*)&h[r * 64 + k]
                                     : make_float4(0.f, 0.f, 0.f, 0.f);
#pragma unroll
            for (int j = 0; j < 4; j++) {
                acc[i][j] += a.x * b[j].x;
                acc[i][j] += a.y * b[j].y;
                acc[i][j] += a.z * b[j].z;
                acc[i][j] += a.w * b[j].w;
            }
        }
    }

#pragma unroll
    for (int i = 0; i < 4; i++) {
        int r = rbase + 16 * i;
        if (r < N_NODES) {
            float dv = g_dis[r];
#pragma unroll
            for (int j = 0; j < 4; j++)
                g_hs2[r * 32 + cbase + 8 * j] = dv * acc[i][j];
        }
    }
}

// ---------------- gather layer 2 (+final scale): one warp per node -----------
__global__ void k_gather2(float* __restrict__ out) {
    int w = (blockIdx.x * blockDim.x + threadIdx.x) >> 5;
    if (w >= N_NODES) return;
    int lane = threadIdx.x & 31;
    const float* __restrict__ hs2 = g_hs2;
    const int* __restrict__ cs = g_csr_src;

    float acc = hs2[w * 32 + lane];
    int beg = g_offs[w], end = g_offs[w + 1];

    for (int base = beg; base < end; base += 32) {
        int n = end - base;
        int idx = (base + lane < end) ? cs[base + lane] : 0;
        if (n >= 32) {
#pragma unroll
            for (int i = 0; i < 32; i++) {
                int s = __shfl_sync(0xffffffffu, idx, i);
                acc += hs2[s * 32 + lane];
            }
        } else {
            for (int i = 0; i < n; i++) {
                int s = __shfl_sync(0xffffffffu, idx, i);
                acc += hs2[s * 32 + lane];
            }
        }
    }

    out[w * 32 + lane] = g_dis[w] * acc;
}

// ---------------- launch ------------------------------------------------------
extern "C" void kernel_launch(void* const* d_in, const int* in_sizes, int n_in,
                              void* d_out, int out_size) {
    const float* x  = (const float*)d_in[0];
    const int*   ei = (const int*)d_in[1];
    const float* W1 = (const float*)d_in[2];
    const float* W2 = (const float*)d_in[3];

    float* out  = (float*)d_out;          // [N,32]
    float* hout = out + N_NODES * 32;     // [N,64]

    int E = in_sizes[1] / 2;
    if (E > E_MAX) E = E_MAX;

    k_prep_edges<<<(E + 255) / 256, 256>>>(ei, E);          // 1
    k_scanA<<<NBLK, 256>>>();                               // 2
    k_scanB<<<NBLK, 256>>>();                               // 3
    k_gemm1<<<(N_NODES + 127) / 128, 256>>>(x, W1);         // 4  <- ncu capture
    k_bucket<<<(E + 255) / 256, 256>>>(E);                  // 5
    k_gather1<<<(N_NODES * 32 + 255) / 256, 256>>>(hout);   // 6
    k_gemm2<<<(N_NODES + 63) / 64, 128>>>(hout, W2);        // 7
    k_gather2<<<(N_NODES * 32 + 255) / 256, 256>>>(out);    // 8
}

// round 11
// speedup vs baseline: 1.9264x; 1.0845x over previous
#include <cuda_runtime.h>

#define N_NODES 50000
#define E_MAX   1600000
#define NBLK    ((N_NODES + 255) / 256)   // 196

// ---------------- scratch (static device globals; no allocation) -------------
__device__ int    g_deg[N_NODES];        // in-degree count; reset to 0 by k_scanB
__device__ int    g_bsum[NBLK];          // per-block degree sums
__device__ float  g_dis[N_NODES];
__device__ int    g_src[E_MAX];
__device__ int    g_dst[E_MAX];
__device__ int    g_offs[N_NODES + 1];   // CSR offsets by dst (real edges only)
__device__ int    g_cur[N_NODES];        // bucket cursors
__device__ int    g_csr_src[E_MAX];      // src ids grouped by dst
__device__ float2 g_hs [N_NODES * 32];   // RAW x@W1 (dis applied in gather1)
__device__ float  g_hs2[N_NODES * 32];   // dis-scaled h@W2, 32 f32/node

// ---------------- stream fork resources (host objects, created once) ---------
namespace {
struct ForkInit {
    cudaStream_t side;
    cudaEvent_t  ev_fork, ev_join;
    ForkInit() {
        cudaStreamCreateWithFlags(&side, cudaStreamNonBlocking);
        cudaEventCreateWithFlags(&ev_fork, cudaEventDisableTiming);
        cudaEventCreateWithFlags(&ev_join, cudaEventDisableTiming);
    }
};
ForkInit g_fork;
}

// ---------------- prep: dtype detect + edge parse + degree count -------------
__global__ void k_prep_edges(const int* __restrict__ p, int E) {
    __shared__ int s_nonzero;
    if (threadIdx.x == 0) s_nonzero = 0;
    __syncthreads();
    if (threadIdx.x < 256) {
        if (p[2 * threadIdx.x + 1] != 0) atomicOr(&s_nonzero, 1);
    }
    __syncthreads();
    int i64 = (s_nonzero == 0);

    int e = blockIdx.x * blockDim.x + threadIdx.x;
    if (e >= E) return;
    int s, d;
    if (i64) { s = p[2 * e]; d = p[2 * (E + e)]; }
    else     { s = p[e];     d = p[E + e]; }
    if ((unsigned)s >= N_NODES) s = 0;
    if ((unsigned)d >= N_NODES) d = 0;
    g_src[e] = s;
    g_dst[e] = d;
    atomicAdd(&g_deg[d], 1);
}

// ---------------- scan phase A: per-block degree sums ------------------------
__global__ void k_scanA() {
    __shared__ int red[256];
    int t = threadIdx.x;
    int i = blockIdx.x * 256 + t;
    red[t] = (i < N_NODES) ? g_deg[i] : 0;
    __syncthreads();
#pragma unroll
    for (int off = 128; off > 0; off >>= 1) {
        if (t < off) red[t] += red[t + off];
        __syncthreads();
    }
    if (t == 0) g_bsum[blockIdx.x] = red[0];
}

// ---------------- scan phase B: block prefix + local scan + writes -----------
__global__ void k_scanB() {
    __shared__ int red[256];
    __shared__ int sc[256];
    int t = threadIdx.x;
    int b = blockIdx.x;

    red[t] = (t < b) ? g_bsum[t] : 0;     // NBLK=196 < 256
    __syncthreads();
#pragma unroll
    for (int off = 128; off > 0; off >>= 1) {
        if (t < off) red[t] += red[t + off];
        __syncthreads();
    }
    int block_off = red[0];

    int i = b * 256 + t;
    int d = (i < N_NODES) ? g_deg[i] : 0;
    sc[t] = d;
    __syncthreads();
#pragma unroll
    for (int off = 1; off < 256; off <<= 1) {
        int v = (t >= off) ? sc[t - off] : 0;
        __syncthreads();
        sc[t] += v;
        __syncthreads();
    }
    int off = block_off + sc[t] - d;      // exclusive

    if (i < N_NODES) {
        g_offs[i] = off;
        g_cur[i]  = off;
        g_dis[i]  = rsqrtf((float)(d + 1));   // +1 = self loop
        g_deg[i]  = 0;                        // restore zero-state invariant
        if (i == N_NODES - 1) g_offs[N_NODES] = off + d;
    }
}

// ---------------- bucket edges by dst ----------------------------------------
__global__ void k_bucket(int E) {
    int e = blockIdx.x * blockDim.x + threadIdx.x;
    if (e >= E) return;
    int d = g_dst[e];
    int pos = atomicAdd(&g_cur[d], 1);
    g_csr_src[pos] = g_src[e];
}

// ---------------- GEMM1: hs = x @ W1 (RAW, no dis dependency) ----------------
// 256 threads, 128x64 tile, thread = 4 rows x 8 cols.
__global__ void k_gemm1(const float* __restrict__ x, const float* __restrict__ W) {
    __shared__ float sWT[64 * 132];
    int t = threadIdx.x;                     // 0..255
    for (int idx = t; idx < 128 * 64; idx += 256) {
        int k = idx >> 6, c = idx & 63;
        sWT[c * 132 + k] = W[idx];
    }
    __syncthreads();

    int rbase = blockIdx.x * 128 + (t >> 3); // + 32*i, i<4
    int cbase = t & 7;                       // + 8*j, j<8
    float acc[4][8];
#pragma unroll
    for (int i = 0; i < 4; i++)
#pragma unroll
        for (int j = 0; j < 8; j++) acc[i][j] = 0.f;

    for (int k = 0; k < 128; k += 4) {
        float4 b[8];
#pragma unroll
        for (int j = 0; j < 8; j++)
            b[j] = *(const float4*)&sWT[(cbase + 8 * j) * 132 + k];
#pragma unroll
        for (int i = 0; i < 4; i++) {
            int r = rbase + 32 * i;
            float4 a = (r < N_NODES) ? *(const float4*)&x[r * 128 + k]
                                     : make_float4(0.f, 0.f, 0.f, 0.f);
#pragma unroll
            for (int j = 0; j < 8; j++) {
                acc[i][j] += a.x * b[j].x;
                acc[i][j] += a.y * b[j].y;
                acc[i][j] += a.z * b[j].z;
                acc[i][j] += a.w * b[j].w;
            }
        }
    }

    float* hs = (float*)g_hs;
#pragma unroll
    for (int i = 0; i < 4; i++) {
        int r = rbase + 32 * i;
        if (r < N_NODES) {
#pragma unroll
            for (int j = 0; j < 8; j++)
                hs[r * 64 + cbase + 8 * j] = acc[i][j];
        }
    }
}

// ---------------- gather layer 1 (+dis fold +tanh): one warp per node --------
__global__ void k_gather1(float* __restrict__ hout) {
    int w = (blockIdx.x * blockDim.x + threadIdx.x) >> 5;   // node
    if (w >= N_NODES) return;
    int lane = threadIdx.x & 31;
    const float2* __restrict__ hs = g_hs;
    const int* __restrict__ cs = g_csr_src;
    const float* __restrict__ dis = g_dis;

    float dv = dis[w];
    float2 acc = hs[w * 32 + lane];              // self-loop: dis[w]*hsr[w]
    acc.x *= dv; acc.y *= dv;

    int beg = g_offs[w], end = g_offs[w + 1];
    for (int base = beg; base < end; base += 32) {
        int n = end - base;
        int pos = base + lane;
        int idx = (pos < end) ? cs[pos] : 0;
        float ds = dis[idx];
        if (n >= 32) {
#pragma unroll
            for (int i = 0; i < 32; i++) {
                int   s = __shfl_sync(0xffffffffu, idx, i);
                float f = __shfl_sync(0xffffffffu, ds, i);
                float2 a = hs[s * 32 + lane];
                acc.x = fmaf(f, a.x, acc.x);
                acc.y = fmaf(f, a.y, acc.y);
            }
        } else {
            for (int i = 0; i < n; i++) {
                int   s = __shfl_sync(0xffffffffu, idx, i);
                float f = __shfl_sync(0xffffffffu, ds, i);
                float2 a = hs[s * 32 + lane];
                acc.x = fmaf(f, a.x, acc.x);
                acc.y = fmaf(f, a.y, acc.y);
            }
        }
    }

    float2 o;
    o.x = tanhf(dv * acc.x);
    o.y = tanhf(dv * acc.y);
    ((float2*)hout)[w * 32 + lane] = o;
}

// ---------------- GEMM2: hs2 = dis * (h @ W2) --------------------------------
__global__ void k_gemm2(const float* __restrict__ h, const float* __restrict__ W) {
    __shared__ float sWT[32 * 68];
    int t = threadIdx.x;                         // 0..127
    for (int idx = t; idx < 64 * 32; idx += 128) {
        int k = idx >> 5, c = idx & 31;
        sWT[c * 68 + k] = W[idx];
    }
    __syncthreads();

    int rbase = blockIdx.x * 64 + (t >> 3);
    int cbase = t & 7;
    float acc[4][4];
#pragma unroll
    for (int i = 0; i < 4; i++)
#pragma unroll
        for (int j = 0; j < 4; j++) acc[i][j] = 0.f;

    for (int k = 0; k < 64; k += 4) {
        float4 b[4];
#pragma unroll
        for (int j = 0; j < 4; j++)
            b[j] = *(const float4*)&sWT[(cbase + 8 * j) * 68 + k];
#pragma unroll
        for (int i = 0; i < 4; i++) {
            int r = rbase + 16 * i;
            float4 a = (r < N_NODES) ? *(const float4*)&h[r * 64 + k]
                                     : make_float4(0.f, 0.f, 0.f, 0.f);
#pragma unroll
            for (int j = 0; j < 4; j++) {
                acc[i][j] += a.x * b[j].x;
                acc[i][j] += a.y * b[j].y;
                acc[i][j] += a.z * b[j].z;
                acc[i][j] += a.w * b[j].w;
            }
        }
    }

#pragma unroll
    for (int i = 0; i < 4; i++) {
        int r = rbase + 16 * i;
        if (r < N_NODES) {
            float dv = g_dis[r];
#pragma unroll
            for (int j = 0; j < 4; j++)
                g_hs2[r * 32 + cbase + 8 * j] = dv * acc[i][j];
        }
    }
}

// ---------------- gather layer 2 (+final scale): one warp per node -----------
__global__ void k_gather2(float* __restrict__ out) {
    int w = (blockIdx.x * blockDim.x + threadIdx.x) >> 5;
    if (w >= N_NODES) return;
    int lane = threadIdx.x & 31;
    const float* __restrict__ hs2 = g_hs2;
    const int* __restrict__ cs = g_csr_src;

    float acc = hs2[w * 32 + lane];
    int beg = g_offs[w], end = g_offs[w + 1];

    for (int base = beg; base < end; base += 32) {
        int n = end - base;
        int pos = base + lane;
        int idx = (pos < end) ? cs[pos] : 0;
        if (n >= 32) {
#pragma unroll
            for (int i = 0; i < 32; i++) {
                int s = __shfl_sync(0xffffffffu, idx, i);
                acc += hs2[s * 32 + lane];
            }
        } else {
            for (int i = 0; i < n; i++) {
                int s = __shfl_sync(0xffffffffu, idx, i);
                acc += hs2[s * 32 + lane];
            }
        }
    }

    out[w * 32 + lane] = g_dis[w] * acc;
}

// ---------------- launch ------------------------------------------------------
extern "C" void kernel_launch(void* const* d_in, const int* in_sizes, int n_in,
                              void* d_out, int out_size) {
    const float* x  = (const float*)d_in[0];
    const int*   ei = (const int*)d_in[1];
    const float* W1 = (const float*)d_in[2];
    const float* W2 = (const float*)d_in[3];

    float* out  = (float*)d_out;          // [N,32]
    float* hout = out + N_NODES * 32;     // [N,64]

    int E = in_sizes[1] / 2;
    if (E > E_MAX) E = E_MAX;

    // fork: gemm1 (independent) runs on side stream in parallel with edge chain
    cudaEventRecord(g_fork.ev_fork, 0);
    cudaStreamWaitEvent(g_fork.side, g_fork.ev_fork, 0);

    k_prep_edges<<<(E + 255) / 256, 256>>>(ei, E);                    // 1
    k_scanA<<<NBLK, 256>>>();                                         // 2
    k_scanB<<<NBLK, 256>>>();                                         // 3
    k_bucket<<<(E + 255) / 256, 256>>>(E);                            // 4 <- ncu
    k_gemm1<<<(N_NODES + 127) / 128, 256, 0, g_fork.side>>>(x, W1);   // 5 (side)

    cudaEventRecord(g_fork.ev_join, g_fork.side);
    cudaStreamWaitEvent(0, g_fork.ev_join, 0);

    k_gather1<<<(N_NODES * 32 + 255) / 256, 256>>>(hout);             // 6
    k_gemm2<<<(N_NODES + 63) / 64, 128>>>(hout, W2);                  // 7
    k_gather2<<<(N_NODES * 32 + 255) / 256, 256>>>(out);              // 8
}